// round 11
// baseline (speedup 1.0000x reference)
#include <cuda_runtime.h>
#include <cuda_bf16.h>

typedef unsigned int u32;

// ---------------- problem constants ----------------
#define Tt   7
#define Ff   36
#define Uu   256
#define Bsz  32768
#define BMr  64             // batch rows per CTA (2 m-warp rows x 32)
#define NTm  512            // 16 warps = 2M x 8N
#define NCTA 512            // Bsz / BMr
#define KPAD 304            // 256 h + 36 x + 12 pad = 19 k16 chunks
#define NCH  19
#define SPAD 312            // A row stride in bf16 (conflict-stagger + 16B mult)
#define ROWB (SPAD * 2)     // 624 bytes per A row
#define CHUNKS_PER_STEP 152 // 8 passes x 19 chunks
#define TOTAL_CHUNKS (Tt * CHUNKS_PER_STEP)   // 1064

// ---------------- smem layout (A only now) ----------------
#define AH_OFF 0
#define AL_OFF (BMr * ROWB)            // 39936
#define SMEM_TOTAL (2 * BMr * ROWB)    // 79872 (78 KB)

// ---------------- device scratch (static) ----------------
__device__ u32   g_Bfrag[8 * NCH * 2 * 1024];          // frag-ordered B chunks (1.2MB, L2)
__device__ float g_c[(size_t)32 * NCTA * NTm];         // c state scratch
__constant__ int c_pord[8] = {4, 0, 2, 6, 5, 1, 3, 7}; // pass order: g,i,f,o per half

// ---------------- ptx helpers ----------------
__device__ __forceinline__ u32 smem_u32(const void* p) {
    u32 a;
    asm("{ .reg .u64 t; cvta.to.shared.u64 t, %1; cvt.u32.u64 %0, t; }"
        : "=r"(a) : "l"(p));
    return a;
}
__device__ __forceinline__ float fsgm(float z) {
    float e, r;
    asm("ex2.approx.f32 %0, %1;" : "=f"(e) : "f"(-1.4426950408889634f * z));
    asm("rcp.approx.f32 %0, %1;" : "=f"(r) : "f"(1.0f + e));
    return r;
}
__device__ __forceinline__ float ftanh(float z) {
    float e, r;
    asm("ex2.approx.f32 %0, %1;" : "=f"(e) : "f"(-2.8853900817779268f * z));
    asm("rcp.approx.f32 %0, %1;" : "=f"(r) : "f"(1.0f + e));
    return fmaf(2.0f, r, -1.0f);
}
__device__ __forceinline__ void ldm4(u32* r, u32 addr) {
    asm volatile("ldmatrix.sync.aligned.m8n8.x4.shared.b16 {%0,%1,%2,%3}, [%4];"
                 : "=r"(r[0]), "=r"(r[1]), "=r"(r[2]), "=r"(r[3]) : "r"(addr));
}
__device__ __forceinline__ void mma16816(float* d, const u32* a, const u32* b) {
    asm volatile(
        "mma.sync.aligned.m16n8k16.row.col.f32.bf16.bf16.f32 "
        "{%0,%1,%2,%3}, {%4,%5,%6,%7}, {%8,%9}, {%0,%1,%2,%3};"
        : "+f"(d[0]), "+f"(d[1]), "+f"(d[2]), "+f"(d[3])
        : "r"(a[0]), "r"(a[1]), "r"(a[2]), "r"(a[3]), "r"(b[0]), "r"(b[1]));
}

// A store helper: split fp32 into bf16 hi/lo at A[r][k]
__device__ __forceinline__ void a_store(char* sm, int r, int k, float v) {
    __nv_bfloat16 hi = __float2bfloat16(v);
    __nv_bfloat16 lo = __float2bfloat16(v - __bfloat162float(hi));
    int off = r * ROWB + k * 2;
    *reinterpret_cast<__nv_bfloat16*>(sm + AH_OFF + off) = hi;
    *reinterpret_cast<__nv_bfloat16*>(sm + AL_OFF + off) = lo;
}

// ---------------------------------------------------------------------------
// prep: pack W = [Wr;Wk;0] into mma B-fragment order, bf16 hi/lo. (unchanged)
// u32 index: ((p*19+cc)*2+term)*1024 + wn*128 + lane*4 + reg
// ---------------------------------------------------------------------------
__global__ void prep_kernel(const float* __restrict__ Wr,
                            const float* __restrict__ Wk) {
    int idx = blockIdx.x * 512 + threadIdx.x;
    if (idx >= 8 * NCH * 2 * 1024) return;
    int reg  = idx & 3;
    int lane = (idx >> 2) & 31;
    int wn   = (idx >> 7) & 7;
    int rest = idx >> 10;
    int term = rest & 1;
    int pc   = rest >> 1;
    int cc   = pc % NCH;
    int p    = pc / NCH;

    int n    = (p & 1) * 128 + wn * 16 + (reg >> 1) * 8 + (lane >> 2);
    int ncol = (p >> 1) * 256 + n;
    int k0   = cc * 16 + (reg & 1) * 8 + ((lane & 3) << 1);

    float v0 = 0.f, v1 = 0.f;
    if (k0 < 256)      v0 = Wr[(size_t)k0 * 1024 + ncol];
    else if (k0 < 292) v0 = Wk[(size_t)(k0 - 256) * 1024 + ncol];
    int k1 = k0 + 1;
    if (k1 < 256)      v1 = Wr[(size_t)k1 * 1024 + ncol];
    else if (k1 < 292) v1 = Wk[(size_t)(k1 - 256) * 1024 + ncol];

    unsigned short e0, e1;
    if (term == 0) {
        e0 = __bfloat16_as_ushort(__float2bfloat16(v0));
        e1 = __bfloat16_as_ushort(__float2bfloat16(v1));
    } else {
        __nv_bfloat16 h0 = __float2bfloat16(v0);
        __nv_bfloat16 h1 = __float2bfloat16(v1);
        e0 = __bfloat16_as_ushort(__float2bfloat16(v0 - __bfloat162float(h0)));
        e1 = __bfloat16_as_ushort(__float2bfloat16(v1 - __bfloat162float(h1)));
    }
    g_Bfrag[idx] = ((u32)e1 << 16) | (u32)e0;
}

// ---------------------------------------------------------------------------
// main LSTM kernel: barrier-free mainloop; B fragments LDG'd per-warp from L2
// with 1-chunk register prefetch.
// ---------------------------------------------------------------------------
__global__ void __launch_bounds__(NTm, 1)
lstm_hmma(const float* __restrict__ x,    // [B,T,F]
          const float* __restrict__ h0,   // [B,U]
          const float* __restrict__ c0,   // [B,U]
          const float* __restrict__ bia,  // [4U]
          float* __restrict__ out)        // [B,T,U]
{
    extern __shared__ char sm[];
    const u32 smb  = smem_u32(sm);
    const int tid  = threadIdx.x;
    const int lane = tid & 31;
    const int wid  = tid >> 5;
    const int wm   = wid >> 3;       // 0..1  (M warp row)
    const int wn   = wid & 7;        // 0..7  (N warp col)
    const int cta  = blockIdx.x;
    const int row0 = cta * BMr;

    // ---- init A: h0, x(t=0), zero pad ----
    for (int i = tid; i < BMr * Uu; i += NTm) {
        int r = i >> 8, k = i & 255;
        a_store(sm, r, k, h0[(size_t)(row0 + r) * Uu + k]);
    }
    for (int i = tid; i < BMr * Ff; i += NTm) {
        int r = i / Ff, f = i - r * Ff;
        a_store(sm, r, 256 + f, x[(size_t)(row0 + r) * (Tt * Ff) + f]);
    }
    for (int i = tid; i < BMr * (KPAD - 292); i += NTm) {
        int r = i / 12, k = 292 + (i - r * 12);
        a_store(sm, r, k, 0.0f);
    }
    __syncthreads();

    // ldmatrix per-lane base address (A hi, m-tile 0)
    const u32 aBase = smb + AH_OFF
                    + (u32)(wm * 32 + (lane & 15)) * ROWB
                    + (u32)((lane >> 4) * 16);

    // ---- B prefetch state: fragments for the NEXT chunk live in registers ----
    const u32 fragOff = (u32)(wn * 128 + lane * 4);
    int gi = 0;            // chunks prefetched
    int qi = 0, cci = 0;   // (pass, chunk) of next prefetch
    uint4 pfh, pfl;

    auto prefetch = [&]() {
        const u32* base = g_Bfrag
            + ((size_t)(c_pord[qi] * NCH + cci) * 2) * 1024 + fragOff;
        pfh = __ldg(reinterpret_cast<const uint4*>(base));
        pfl = __ldg(reinterpret_cast<const uint4*>(base + 1024));
        gi++;
        if (++cci == NCH) { cci = 0; if (++qi == 8) qi = 0; }
    };
    prefetch();   // chunk 0

    float gv[16], hold[16];

#pragma unroll 1
    for (int t = 0; t < Tt; t++) {
#pragma unroll 1
        for (int q = 0; q < 8; q++) {
            const int pass = c_pord[q];
            const int gate = pass >> 1;
            const int half = pass & 1;

            float acc[2][2][4];
#pragma unroll
            for (int a = 0; a < 2; a++)
#pragma unroll
                for (int b = 0; b < 2; b++)
#pragma unroll
                    for (int e = 0; e < 4; e++) acc[a][b][e] = 0.f;

            // ---- mainloop: 19 k16 chunks, no barriers ----
#pragma unroll 1
            for (int cc = 0; cc < NCH; cc++) {
                // consume prefetched B, kick off next prefetch
                u32 bh[4] = {pfh.x, pfh.y, pfh.z, pfh.w};
                u32 bl[4] = {pfl.x, pfl.y, pfl.z, pfl.w};
                if (gi < TOTAL_CHUNKS) prefetch();

                const u32 ao = aBase + (u32)cc * 32;
                u32 ahi0[4], ahi1[4], alo0[4], alo1[4];
                ldm4(ahi0, ao);
                ldm4(ahi1, ao + 16 * ROWB);
                ldm4(alo0, ao + (AL_OFF - AH_OFF));
                ldm4(alo1, ao + (AL_OFF - AH_OFF) + 16 * ROWB);

#pragma unroll
                for (int nt = 0; nt < 2; nt++) {
                    mma16816(acc[0][nt], ahi0, &bh[nt * 2]);
                    mma16816(acc[1][nt], ahi1, &bh[nt * 2]);
                    mma16816(acc[0][nt], alo0, &bh[nt * 2]);
                    mma16816(acc[1][nt], alo1, &bh[nt * 2]);
                    mma16816(acc[0][nt], ahi0, &bl[nt * 2]);
                    mma16816(acc[1][nt], ahi1, &bl[nt * 2]);
                }
            }

            // ---- per-pass epilogue (registers + gmem c only) ----
            const int pk = q & 3;     // 0:g 1:i 2:f 3:o
#pragma unroll
            for (int j = 0; j < 16; j++) {
                const int mt = j >> 3, nt = (j >> 2) & 1, e = j & 3;
                const int ucol = half * 128 + wn * 16 + nt * 8
                               + 2 * (lane & 3) + (e & 1);
                const int row  = wm * 32 + mt * 16 + (lane >> 2) + ((e >> 1) << 3);
                const float z  = acc[mt][nt][e] + __ldg(bia + gate * 256 + ucol);
                if (pk == 0) {
                    gv[j] = ftanh(z);
                } else if (pk == 1) {
                    gv[j] *= fsgm(z);
                } else if (pk == 2) {
                    const size_t ci = (size_t)(half * 16 + j) * ((size_t)NCTA * NTm)
                                    + (size_t)cta * NTm + tid;
                    const float cold = (t == 0)
                        ? __ldg(c0 + (size_t)(row0 + row) * Uu + ucol)
                        : g_c[ci];
                    const float cn = fsgm(z) * cold + gv[j];
                    g_c[ci] = cn;
                    gv[j] = ftanh(cn);
                } else {
                    gv[j] = fsgm(z) * gv[j];   // h value
                }
            }

            if (pk == 3) {
                // write h to out (float2 pairs share a row)
#pragma unroll
                for (int jp = 0; jp < 8; jp++) {
                    const int j  = 2 * jp;
                    const int mt = j >> 3, nt = (j >> 2) & 1, e = j & 3;
                    const int ucol = half * 128 + wn * 16 + nt * 8 + 2 * (lane & 3);
                    const int row  = wm * 32 + mt * 16 + (lane >> 2) + ((e >> 1) << 3);
                    *reinterpret_cast<float2*>(
                        out + ((size_t)(row0 + row) * Tt + t) * Uu + ucol) =
                        make_float2(gv[j], gv[j + 1]);
                }
                if (half == 0) {
#pragma unroll
                    for (int j = 0; j < 16; j++) hold[j] = gv[j];
                }
            }
        } // q passes

        // ---- step boundary: write h (both halves) back into A, load x(t+1) ----
        __syncthreads();   // all A reads of this step complete
#pragma unroll
        for (int j = 0; j < 16; j++) {
            const int mt = j >> 3, nt = (j >> 2) & 1, e = j & 3;
            const int loc = wn * 16 + nt * 8 + 2 * (lane & 3) + (e & 1);
            const int row = wm * 32 + mt * 16 + (lane >> 2) + ((e >> 1) << 3);
            a_store(sm, row, 128 + loc, gv[j]);     // half 1
            a_store(sm, row, loc,       hold[j]);   // half 0
        }
        if (t + 1 < Tt) {
            for (int i = tid; i < BMr * Ff; i += NTm) {
                int r = i / Ff, f = i - r * Ff;
                a_store(sm, r, 256 + f,
                        x[((size_t)(row0 + r) * Tt + (t + 1)) * Ff + f]);
            }
        }
        __syncthreads();
    } // t
}

// ---------------------------------------------------------------------------
// Harness entry point
// ---------------------------------------------------------------------------
extern "C" void kernel_launch(void* const* d_in, const int* in_sizes, int n_in,
                              void* d_out, int out_size) {
    const float* x  = (const float*)d_in[0];  // [B,T,F]
    const float* h0 = (const float*)d_in[1];  // [B,U]
    const float* c0 = (const float*)d_in[2];  // [B,U]
    const float* Wk = (const float*)d_in[3];  // [F,4U]
    const float* Wr = (const float*)d_in[4];  // [U,4U]
    const float* b  = (const float*)d_in[5];  // [4U]
    float* out = (float*)d_out;               // [B,T,U]

    prep_kernel<<<(8 * NCH * 2 * 1024 + 511) / 512, 512>>>(Wr, Wk);

    cudaFuncSetAttribute(lstm_hmma,
                         cudaFuncAttributeMaxDynamicSharedMemorySize, SMEM_TOTAL);
    lstm_hmma<<<NCTA, NTm, SMEM_TOTAL>>>(x, h0, c0, b, out);
}

// round 12
// speedup vs baseline: 1.4911x; 1.4911x over previous
#include <cuda_runtime.h>
#include <cuda_bf16.h>

typedef unsigned int u32;

// ---------------- problem constants ----------------
#define Tt   7
#define Ff   36
#define Uu   256
#define Bsz  32768
#define BMr  64             // batch rows per CTA (2 m-warp rows x 32)
#define NTm  512            // 16 warps = 2M x 8N
#define NCTA 512            // Bsz / BMr
#define KPAD 304            // 256 h + 36 x + 12 pad = 19 k16 chunks
#define NCH  19
#define SPAD 312            // A row stride in bf16
#define ROWB (SPAD * 2)     // 624 bytes per A row
#define CPS  (4 * NCH)      // 76 chunks per step (4 fused sweeps x 19)

// ---------------- smem layout ----------------
#define AH_OFF   0
#define AL_OFF   (BMr * ROWB)            // 39936
#define HOLD_OFF (2 * BMr * ROWB)        // 79872 (half-0 h buffer, 32KB)
#define SMEM_TOTAL (HOLD_OFF + NTm * 16 * 4)   // 112640

// ---------------- device scratch (static) ----------------
// B fragments in CONSUMPTION order: [(s*19+cc)*4 + gsel*2+term]*1024 + wn*128+lane*4+reg
__device__ u32   g_Bfrag[4 * NCH * 4 * 1024];          // 1.2MB, L2-resident
__device__ float g_c[(size_t)32 * NCTA * NTm];         // c state scratch

// ---------------- ptx helpers ----------------
__device__ __forceinline__ u32 smem_u32(const void* p) {
    u32 a;
    asm("{ .reg .u64 t; cvta.to.shared.u64 t, %1; cvt.u32.u64 %0, t; }"
        : "=r"(a) : "l"(p));
    return a;
}
__device__ __forceinline__ float fsgm(float z) {
    float e, r;
    asm("ex2.approx.f32 %0, %1;" : "=f"(e) : "f"(-1.4426950408889634f * z));
    asm("rcp.approx.f32 %0, %1;" : "=f"(r) : "f"(1.0f + e));
    return r;
}
__device__ __forceinline__ float ftanh(float z) {
    float e, r;
    asm("ex2.approx.f32 %0, %1;" : "=f"(e) : "f"(-2.8853900817779268f * z));
    asm("rcp.approx.f32 %0, %1;" : "=f"(r) : "f"(1.0f + e));
    return fmaf(2.0f, r, -1.0f);
}
__device__ __forceinline__ void ldm4(u32* r, u32 addr) {
    asm volatile("ldmatrix.sync.aligned.m8n8.x4.shared.b16 {%0,%1,%2,%3}, [%4];"
                 : "=r"(r[0]), "=r"(r[1]), "=r"(r[2]), "=r"(r[3]) : "r"(addr));
}
__device__ __forceinline__ void mma16816(float* d, const u32* a, const u32* b) {
    asm volatile(
        "mma.sync.aligned.m16n8k16.row.col.f32.bf16.bf16.f32 "
        "{%0,%1,%2,%3}, {%4,%5,%6,%7}, {%8,%9}, {%0,%1,%2,%3};"
        : "+f"(d[0]), "+f"(d[1]), "+f"(d[2]), "+f"(d[3])
        : "r"(a[0]), "r"(a[1]), "r"(a[2]), "r"(a[3]), "r"(b[0]), "r"(b[1]));
}
__device__ __forceinline__ void ldg4(u32* r, const u32* p) {
    asm volatile("ld.global.nc.v4.u32 {%0,%1,%2,%3}, [%4];"
                 : "=r"(r[0]), "=r"(r[1]), "=r"(r[2]), "=r"(r[3]) : "l"(p));
}

// A store helper: split fp32 into bf16 hi/lo at A[r][k]
__device__ __forceinline__ void a_store(char* sm, int r, int k, float v) {
    __nv_bfloat16 hi = __float2bfloat16(v);
    __nv_bfloat16 lo = __float2bfloat16(v - __bfloat162float(hi));
    int off = r * ROWB + k * 2;
    *reinterpret_cast<__nv_bfloat16*>(sm + AH_OFF + off) = hi;
    *reinterpret_cast<__nv_bfloat16*>(sm + AL_OFF + off) = lo;
}

// ---------------------------------------------------------------------------
// prep: pack W = [Wr;Wk;0] into mma B-fragment order, bf16 hi/lo,
// grouped by fused sweep: s in 0..3 -> half = s>>1, pair = s&1;
// pair 0 -> gates (i=0, g=2); pair 1 -> gates (f=1, o=3).
// ---------------------------------------------------------------------------
__global__ void prep_kernel(const float* __restrict__ Wr,
                            const float* __restrict__ Wk) {
    int idx = blockIdx.x * 512 + threadIdx.x;
    if (idx >= 4 * NCH * 4 * 1024) return;
    int reg  = idx & 3;
    int lane = (idx >> 2) & 31;
    int wn   = (idx >> 7) & 7;
    int rest = idx >> 10;
    int sub  = rest & 3;           // gsel*2 + term
    int bc   = rest >> 2;
    int cc   = bc % NCH;
    int s    = bc / NCH;           // 0..3

    int term = sub & 1;
    int gsel = sub >> 1;
    int half = s >> 1;
    int pair = s & 1;
    int gate = (pair == 0) ? (gsel ? 2 : 0) : (gsel ? 3 : 1);

    int n_local = wn * 16 + (reg >> 1) * 8 + (lane >> 2);
    int ncol    = gate * 256 + half * 128 + n_local;
    int k0      = cc * 16 + (reg & 1) * 8 + ((lane & 3) << 1);

    float v0 = 0.f, v1 = 0.f;
    if (k0 < 256)      v0 = Wr[(size_t)k0 * 1024 + ncol];
    else if (k0 < 292) v0 = Wk[(size_t)(k0 - 256) * 1024 + ncol];
    int k1 = k0 + 1;
    if (k1 < 256)      v1 = Wr[(size_t)k1 * 1024 + ncol];
    else if (k1 < 292) v1 = Wk[(size_t)(k1 - 256) * 1024 + ncol];

    unsigned short e0, e1;
    if (term == 0) {
        e0 = __bfloat16_as_ushort(__float2bfloat16(v0));
        e1 = __bfloat16_as_ushort(__float2bfloat16(v1));
    } else {
        __nv_bfloat16 h0 = __float2bfloat16(v0);
        __nv_bfloat16 h1 = __float2bfloat16(v1);
        e0 = __bfloat16_as_ushort(__float2bfloat16(v0 - __bfloat162float(h0)));
        e1 = __bfloat16_as_ushort(__float2bfloat16(v1 - __bfloat162float(h1)));
    }
    g_Bfrag[idx] = ((u32)e1 << 16) | (u32)e0;
}

// ---------------------------------------------------------------------------
// main LSTM kernel: 4 fused sweeps per step, 2 gates per sweep (24 HMMA/chunk)
// ---------------------------------------------------------------------------
__global__ void __launch_bounds__(NTm, 1)
lstm_hmma(const float* __restrict__ x,    // [B,T,F]
          const float* __restrict__ h0,   // [B,U]
          const float* __restrict__ c0,   // [B,U]
          const float* __restrict__ bia,  // [4U]
          float* __restrict__ out)        // [B,T,U]
{
    extern __shared__ char sm[];
    const u32 smb  = smem_u32(sm);
    const int tid  = threadIdx.x;
    const int lane = tid & 31;
    const int wid  = tid >> 5;
    const int wm   = wid >> 3;       // 0..1  (M warp row)
    const int wn   = wid & 7;        // 0..7  (N warp col)
    const int cta  = blockIdx.x;
    const int row0 = cta * BMr;
    float* holdSm = reinterpret_cast<float*>(sm + HOLD_OFF) + tid * 16;

    // ---- init A: h0, x(t=0), zero pad ----
    for (int i = tid; i < BMr * Uu; i += NTm) {
        int r = i >> 8, k = i & 255;
        a_store(sm, r, k, h0[(size_t)(row0 + r) * Uu + k]);
    }
    for (int i = tid; i < BMr * Ff; i += NTm) {
        int r = i / Ff, f = i - r * Ff;
        a_store(sm, r, 256 + f, x[(size_t)(row0 + r) * (Tt * Ff) + f]);
    }
    for (int i = tid; i < BMr * (KPAD - 292); i += NTm) {
        int r = i / 12, k = 292 + (i - r * 12);
        a_store(sm, r, k, 0.0f);
    }
    __syncthreads();

    // ldmatrix per-lane base address (A hi, m-tile 0)
    const u32 aBase = smb + AH_OFF
                    + (u32)(wm * 32 + (lane & 15)) * ROWB
                    + (u32)((lane >> 4) * 16);

    // ---- B prefetch: 16 u32 fragments for the current chunk, 1 ahead ----
    const u32* bBase = g_Bfrag + (wn * 128 + lane * 4);
    int pi = 0;
    u32 pf[16];
    {
        ldg4(&pf[0],  bBase);
        ldg4(&pf[4],  bBase + 1024);
        ldg4(&pf[8],  bBase + 2048);
        ldg4(&pf[12], bBase + 3072);
        pi = 1;
    }

    float gv[16];

#pragma unroll 1
    for (int t = 0; t < Tt; t++) {
#pragma unroll 1
        for (int s = 0; s < 4; s++) {
            const int half = s >> 1;
            const int pair = s & 1;

            float acc[2][2][2][4];   // [gate][mt][nt][e]
#pragma unroll
            for (int g = 0; g < 2; g++)
#pragma unroll
                for (int a = 0; a < 2; a++)
#pragma unroll
                    for (int b = 0; b < 2; b++)
#pragma unroll
                        for (int e = 0; e < 4; e++) acc[g][a][b][e] = 0.f;

            // ---- mainloop: 19 k16 chunks, 24 HMMA each, no barriers ----
#pragma unroll 1
            for (int cc = 0; cc < NCH; cc++) {
                const u32 ao = aBase + (u32)cc * 32;
                u32 ahi0[4], ahi1[4], alo0[4], alo1[4];
                ldm4(ahi0, ao);
                ldm4(ahi1, ao + 16 * ROWB);
                ldm4(alo0, ao + (AL_OFF - AH_OFF));
                ldm4(alo1, ao + (AL_OFF - AH_OFF) + 16 * ROWB);

                // consume pf directly (B for this chunk)
#pragma unroll
                for (int g = 0; g < 2; g++)
#pragma unroll
                    for (int nt = 0; nt < 2; nt++) {
                        mma16816(acc[g][0][nt], ahi0, &pf[g * 8 + nt * 2]);
                        mma16816(acc[g][1][nt], ahi1, &pf[g * 8 + nt * 2]);
                        mma16816(acc[g][0][nt], alo0, &pf[g * 8 + nt * 2]);
                        mma16816(acc[g][1][nt], alo1, &pf[g * 8 + nt * 2]);
                        mma16816(acc[g][0][nt], ahi0, &pf[g * 8 + 4 + nt * 2]);
                        mma16816(acc[g][1][nt], ahi1, &pf[g * 8 + 4 + nt * 2]);
                    }

                // prefetch next chunk (sequential consumption order)
                const u32* p = bBase + (size_t)pi * 4096;
                ldg4(&pf[0],  p);
                ldg4(&pf[4],  p + 1024);
                ldg4(&pf[8],  p + 2048);
                ldg4(&pf[12], p + 3072);
                pi = (pi == CPS - 1) ? 0 : pi + 1;
            }

            // ---- fused epilogue ----
            const int g0 = pair ? 1 : 0;   // i or f
            const int g1 = pair ? 3 : 2;   // g or o
#pragma unroll
            for (int j = 0; j < 16; j++) {
                const int mt = j >> 3, nt = (j >> 2) & 1, e = j & 3;
                const int ucol = half * 128 + wn * 16 + nt * 8
                               + 2 * (lane & 3) + (e & 1);
                const int row  = wm * 32 + mt * 16 + (lane >> 2) + ((e >> 1) << 3);
                const float z0 = acc[0][mt][nt][e] + __ldg(bia + g0 * 256 + ucol);
                const float z1 = acc[1][mt][nt][e] + __ldg(bia + g1 * 256 + ucol);
                if (pair == 0) {
                    gv[j] = fsgm(z0) * ftanh(z1);      // sigma(i)*tanh(g)
                } else {
                    const size_t ci = (size_t)(half * 16 + j) * ((size_t)NCTA * NTm)
                                    + (size_t)cta * NTm + tid;
                    const float cold = (t == 0)
                        ? __ldg(c0 + (size_t)(row0 + row) * Uu + ucol)
                        : g_c[ci];
                    const float cn = fsgm(z0) * cold + gv[j];
                    g_c[ci] = cn;
                    gv[j] = fsgm(z1) * ftanh(cn);      // h = sigma(o)*tanh(c)
                }
            }

            if (pair == 1) {
                // write h to out (float2 pairs share a row)
#pragma unroll
                for (int jp = 0; jp < 8; jp++) {
                    const int j  = 2 * jp;
                    const int mt = j >> 3, nt = (j >> 2) & 1, e = j & 3;
                    const int ucol = half * 128 + wn * 16 + nt * 8 + 2 * (lane & 3);
                    const int row  = wm * 32 + mt * 16 + (lane >> 2) + ((e >> 1) << 3);
                    *reinterpret_cast<float2*>(
                        out + ((size_t)(row0 + row) * Tt + t) * Uu + ucol) =
                        make_float2(gv[j], gv[j + 1]);
                }
                if (half == 0) {   // stash half-0 h in smem until step end
#pragma unroll
                    for (int q = 0; q < 4; q++)
                        *reinterpret_cast<float4*>(holdSm + 4 * q) =
                            make_float4(gv[4 * q], gv[4 * q + 1],
                                        gv[4 * q + 2], gv[4 * q + 3]);
                }
            }
        } // sweeps

        // ---- step boundary: write h (both halves) back into A, load x(t+1) ----
        __syncthreads();   // all A reads of this step complete
#pragma unroll
        for (int j = 0; j < 16; j++) {
            const int mt = j >> 3, nt = (j >> 2) & 1, e = j & 3;
            const int loc = wn * 16 + nt * 8 + 2 * (lane & 3) + (e & 1);
            const int row = wm * 32 + mt * 16 + (lane >> 2) + ((e >> 1) << 3);
            a_store(sm, row, 128 + loc, gv[j]);        // half 1 (in regs)
            a_store(sm, row, loc,       holdSm[j]);    // half 0 (from smem)
        }
        if (t + 1 < Tt) {
            for (int i = tid; i < BMr * Ff; i += NTm) {
                int r = i / Ff, f = i - r * Ff;
                a_store(sm, r, 256 + f,
                        x[((size_t)(row0 + r) * Tt + (t + 1)) * Ff + f]);
            }
        }
        __syncthreads();
    } // t
}

// ---------------------------------------------------------------------------
// Harness entry point
// ---------------------------------------------------------------------------
extern "C" void kernel_launch(void* const* d_in, const int* in_sizes, int n_in,
                              void* d_out, int out_size) {
    const float* x  = (const float*)d_in[0];  // [B,T,F]
    const float* h0 = (const float*)d_in[1];  // [B,U]
    const float* c0 = (const float*)d_in[2];  // [B,U]
    const float* Wk = (const float*)d_in[3];  // [F,4U]
    const float* Wr = (const float*)d_in[4];  // [U,4U]
    const float* b  = (const float*)d_in[5];  // [4U]
    float* out = (float*)d_out;               // [B,T,U]

    prep_kernel<<<(4 * NCH * 4 * 1024 + 511) / 512, 512>>>(Wr, Wk);

    cudaFuncSetAttribute(lstm_hmma,
                         cudaFuncAttributeMaxDynamicSharedMemorySize, SMEM_TOTAL);
    lstm_hmma<<<NCTA, NTm, SMEM_TOTAL>>>(x, h0, c0, b, out);
}

// round 13
// speedup vs baseline: 1.7215x; 1.1545x over previous
#include <cuda_runtime.h>
#include <cuda_bf16.h>

typedef unsigned int u32;

// ---------------- problem constants ----------------
#define Tt   7
#define Ff   36
#define Uu   256
#define Bsz  32768
#define BMr  64             // batch rows per CTA (2 m-warp rows x 32)
#define NTm  512            // 16 warps = 2M x 8N
#define NCTA 512            // Bsz / BMr
#define KPAD 320            // 256 h + 36 x + 28 pad = 20 k16 chunks (EVEN)
#define NCH  20
#define SPAD 328            // A row stride in bf16: 656B = 16B-aligned, staggered
#define ROWB (SPAD * 2)     // 656 bytes per A row
#define CPS  (4 * NCH)      // 80 chunks per step (4 fused sweeps x 20)

// ---------------- smem layout ----------------
#define AH_OFF   0
#define AL_OFF   (BMr * ROWB)            // 41984
#define HOLD_OFF (2 * BMr * ROWB)        // 83968 (half-0 h buffer, 32KB)
#define SMEM_TOTAL (HOLD_OFF + NTm * 16 * 4)   // 116736

// ---------------- device scratch (static) ----------------
// B fragments in CONSUMPTION order:
// [(s*NCH+cc)*4 + gsel*2+term]*1024 + wn*128 + lane*4 + reg
__device__ u32   g_Bfrag[4 * NCH * 4 * 1024];          // 1.31MB, L2-resident
__device__ float g_c[(size_t)32 * NCTA * NTm];         // c state scratch

// ---------------- ptx helpers ----------------
__device__ __forceinline__ u32 smem_u32(const void* p) {
    u32 a;
    asm("{ .reg .u64 t; cvta.to.shared.u64 t, %1; cvt.u32.u64 %0, t; }"
        : "=r"(a) : "l"(p));
    return a;
}
__device__ __forceinline__ float fsgm(float z) {
    float e, r;
    asm("ex2.approx.f32 %0, %1;" : "=f"(e) : "f"(-1.4426950408889634f * z));
    asm("rcp.approx.f32 %0, %1;" : "=f"(r) : "f"(1.0f + e));
    return r;
}
__device__ __forceinline__ float ftanh(float z) {
    float e, r;
    asm("ex2.approx.f32 %0, %1;" : "=f"(e) : "f"(-2.8853900817779268f * z));
    asm("rcp.approx.f32 %0, %1;" : "=f"(r) : "f"(1.0f + e));
    return fmaf(2.0f, r, -1.0f);
}
__device__ __forceinline__ void ldm4(u32* r, u32 addr) {
    asm volatile("ldmatrix.sync.aligned.m8n8.x4.shared.b16 {%0,%1,%2,%3}, [%4];"
                 : "=r"(r[0]), "=r"(r[1]), "=r"(r[2]), "=r"(r[3]) : "r"(addr));
}
__device__ __forceinline__ void mma16816(float* d, const u32* a, const u32* b) {
    asm volatile(
        "mma.sync.aligned.m16n8k16.row.col.f32.bf16.bf16.f32 "
        "{%0,%1,%2,%3}, {%4,%5,%6,%7}, {%8,%9}, {%0,%1,%2,%3};"
        : "+f"(d[0]), "+f"(d[1]), "+f"(d[2]), "+f"(d[3])
        : "r"(a[0]), "r"(a[1]), "r"(a[2]), "r"(a[3]), "r"(b[0]), "r"(b[1]));
}
__device__ __forceinline__ void ldg4(u32* r, const u32* p) {
    asm volatile("ld.global.nc.v4.u32 {%0,%1,%2,%3}, [%4];"
                 : "=r"(r[0]), "=r"(r[1]), "=r"(r[2]), "=r"(r[3]) : "l"(p));
}

// A store helper: split fp32 into bf16 hi/lo at A[r][k]
__device__ __forceinline__ void a_store(char* sm, int r, int k, float v) {
    __nv_bfloat16 hi = __float2bfloat16(v);
    __nv_bfloat16 lo = __float2bfloat16(v - __bfloat162float(hi));
    int off = r * ROWB + k * 2;
    *reinterpret_cast<__nv_bfloat16*>(sm + AH_OFF + off) = hi;
    *reinterpret_cast<__nv_bfloat16*>(sm + AL_OFF + off) = lo;
}

// ---------------------------------------------------------------------------
// prep: pack W = [Wr;Wk;0] into mma B-fragment order, bf16 hi/lo,
// grouped by fused sweep: s in 0..3 -> half = s>>1, pair = s&1;
// pair 0 -> gates (i=0, g=2); pair 1 -> gates (f=1, o=3).
// ---------------------------------------------------------------------------
__global__ void prep_kernel(const float* __restrict__ Wr,
                            const float* __restrict__ Wk) {
    int idx = blockIdx.x * 512 + threadIdx.x;
    if (idx >= 4 * NCH * 4 * 1024) return;
    int reg  = idx & 3;
    int lane = (idx >> 2) & 31;
    int wn   = (idx >> 7) & 7;
    int rest = idx >> 10;
    int sub  = rest & 3;           // gsel*2 + term
    int bc   = rest >> 2;
    int cc   = bc % NCH;
    int s    = bc / NCH;           // 0..3

    int term = sub & 1;
    int gsel = sub >> 1;
    int half = s >> 1;
    int pair = s & 1;
    int gate = (pair == 0) ? (gsel ? 2 : 0) : (gsel ? 3 : 1);

    int n_local = wn * 16 + (reg >> 1) * 8 + (lane >> 2);
    int ncol    = gate * 256 + half * 128 + n_local;
    int k0      = cc * 16 + (reg & 1) * 8 + ((lane & 3) << 1);

    float v0 = 0.f, v1 = 0.f;
    if (k0 < 256)      v0 = Wr[(size_t)k0 * 1024 + ncol];
    else if (k0 < 292) v0 = Wk[(size_t)(k0 - 256) * 1024 + ncol];
    int k1 = k0 + 1;
    if (k1 < 256)      v1 = Wr[(size_t)k1 * 1024 + ncol];
    else if (k1 < 292) v1 = Wk[(size_t)(k1 - 256) * 1024 + ncol];

    unsigned short e0, e1;
    if (term == 0) {
        e0 = __bfloat16_as_ushort(__float2bfloat16(v0));
        e1 = __bfloat16_as_ushort(__float2bfloat16(v1));
    } else {
        __nv_bfloat16 h0 = __float2bfloat16(v0);
        __nv_bfloat16 h1 = __float2bfloat16(v1);
        e0 = __bfloat16_as_ushort(__float2bfloat16(v0 - __bfloat162float(h0)));
        e1 = __bfloat16_as_ushort(__float2bfloat16(v1 - __bfloat162float(h1)));
    }
    g_Bfrag[idx] = ((u32)e1 << 16) | (u32)e0;
}

// chunk-worth of HMMAs consuming buffer pf
#define DO_CHUNK(cc, pf)                                                    \
    do {                                                                    \
        const u32 ao = aBase + (u32)(cc) * 32;                              \
        u32 ahi0[4], ahi1[4], alo0[4], alo1[4];                             \
        ldm4(ahi0, ao);                                                     \
        ldm4(ahi1, ao + 16 * ROWB);                                         \
        ldm4(alo0, ao + (AL_OFF - AH_OFF));                                 \
        ldm4(alo1, ao + (AL_OFF - AH_OFF) + 16 * ROWB);                     \
        _Pragma("unroll")                                                   \
        for (int g = 0; g < 2; g++)                                         \
            _Pragma("unroll")                                               \
            for (int nt = 0; nt < 2; nt++) {                                \
                mma16816(acc[g][0][nt], ahi0, &(pf)[g * 8 + nt * 2]);       \
                mma16816(acc[g][1][nt], ahi1, &(pf)[g * 8 + nt * 2]);       \
                mma16816(acc[g][0][nt], alo0, &(pf)[g * 8 + nt * 2]);       \
                mma16816(acc[g][1][nt], alo1, &(pf)[g * 8 + nt * 2]);       \
                mma16816(acc[g][0][nt], ahi0, &(pf)[g * 8 + 4 + nt * 2]);   \
                mma16816(acc[g][1][nt], ahi1, &(pf)[g * 8 + 4 + nt * 2]);   \
            }                                                               \
    } while (0)

#define PREFETCH(pf)                                                        \
    do {                                                                    \
        const u32* _p = bBase + (size_t)pi * 4096;                          \
        ldg4(&(pf)[0],  _p);                                                \
        ldg4(&(pf)[4],  _p + 1024);                                         \
        ldg4(&(pf)[8],  _p + 2048);                                         \
        ldg4(&(pf)[12], _p + 3072);                                         \
        if (++pi == CPS) pi = 0;                                            \
    } while (0)

// ---------------------------------------------------------------------------
// main LSTM kernel: fused gate pairs + double-buffered B prefetch
// ---------------------------------------------------------------------------
__global__ void __launch_bounds__(NTm, 1)
lstm_hmma(const float* __restrict__ x,    // [B,T,F]
          const float* __restrict__ h0,   // [B,U]
          const float* __restrict__ c0,   // [B,U]
          const float* __restrict__ bia,  // [4U]
          float* __restrict__ out)        // [B,T,U]
{
    extern __shared__ char sm[];
    const u32 smb  = smem_u32(sm);
    const int tid  = threadIdx.x;
    const int lane = tid & 31;
    const int wid  = tid >> 5;
    const int wm   = wid >> 3;       // 0..1  (M warp row)
    const int wn   = wid & 7;        // 0..7  (N warp col)
    const int cta  = blockIdx.x;
    const int row0 = cta * BMr;
    float* holdSm = reinterpret_cast<float*>(sm + HOLD_OFF) + tid * 16;

    // ---- init A: h0, x(t=0), zero pad ----
    for (int i = tid; i < BMr * Uu; i += NTm) {
        int r = i >> 8, k = i & 255;
        a_store(sm, r, k, h0[(size_t)(row0 + r) * Uu + k]);
    }
    for (int i = tid; i < BMr * Ff; i += NTm) {
        int r = i / Ff, f = i - r * Ff;
        a_store(sm, r, 256 + f, x[(size_t)(row0 + r) * (Tt * Ff) + f]);
    }
    for (int i = tid; i < BMr * (KPAD - 292); i += NTm) {
        int r = i / (KPAD - 292), k = 292 + (i - r * (KPAD - 292));
        a_store(sm, r, k, 0.0f);
    }
    __syncthreads();

    // ldmatrix per-lane base address (A hi, m-tile 0)
    const u32 aBase = smb + AH_OFF
                    + (u32)(wm * 32 + (lane & 15)) * ROWB
                    + (u32)((lane >> 4) * 16);

    // ---- B double-buffer: pfA = even chunks, pfB = odd chunks ----
    const u32* bBase = g_Bfrag + (wn * 128 + lane * 4);
    int pi = 0;
    u32 pfA[16], pfB[16];
    PREFETCH(pfA);     // chunk 0
    PREFETCH(pfB);     // chunk 1

    float gv[16];

#pragma unroll 1
    for (int t = 0; t < Tt; t++) {
#pragma unroll 1
        for (int s = 0; s < 4; s++) {
            const int half = s >> 1;
            const int pair = s & 1;

            float acc[2][2][2][4];   // [gate][mt][nt][e]
#pragma unroll
            for (int g = 0; g < 2; g++)
#pragma unroll
                for (int a = 0; a < 2; a++)
#pragma unroll
                    for (int b = 0; b < 2; b++)
#pragma unroll
                        for (int e = 0; e < 4; e++) acc[g][a][b][e] = 0.f;

            // ---- mainloop: 20 chunks, double-buffered, no barriers ----
#pragma unroll 1
            for (int cc = 0; cc < NCH; cc += 2) {
                DO_CHUNK(cc, pfA);       // consume even buffer
                PREFETCH(pfA);           // refill: 2 chunks ahead
                DO_CHUNK(cc + 1, pfB);   // consume odd buffer
                PREFETCH(pfB);
            }

            // ---- fused epilogue ----
            const int g0 = pair ? 1 : 0;   // i or f
            const int g1 = pair ? 3 : 2;   // g or o
#pragma unroll
            for (int j = 0; j < 16; j++) {
                const int mt = j >> 3, nt = (j >> 2) & 1, e = j & 3;
                const int ucol = half * 128 + wn * 16 + nt * 8
                               + 2 * (lane & 3) + (e & 1);
                const int row  = wm * 32 + mt * 16 + (lane >> 2) + ((e >> 1) << 3);
                const float z0 = acc[0][mt][nt][e] + __ldg(bia + g0 * 256 + ucol);
                const float z1 = acc[1][mt][nt][e] + __ldg(bia + g1 * 256 + ucol);
                if (pair == 0) {
                    gv[j] = fsgm(z0) * ftanh(z1);      // sigma(i)*tanh(g)
                } else {
                    const size_t ci = (size_t)(half * 16 + j) * ((size_t)NCTA * NTm)
                                    + (size_t)cta * NTm + tid;
                    const float cold = (t == 0)
                        ? __ldg(c0 + (size_t)(row0 + row) * Uu + ucol)
                        : g_c[ci];
                    const float cn = fsgm(z0) * cold + gv[j];
                    g_c[ci] = cn;
                    gv[j] = fsgm(z1) * ftanh(cn);      // h = sigma(o)*tanh(c)
                }
            }

            if (pair == 1) {
                // write h to out (float2 pairs share a row)
#pragma unroll
                for (int jp = 0; jp < 8; jp++) {
                    const int j  = 2 * jp;
                    const int mt = j >> 3, nt = (j >> 2) & 1, e = j & 3;
                    const int ucol = half * 128 + wn * 16 + nt * 8 + 2 * (lane & 3);
                    const int row  = wm * 32 + mt * 16 + (lane >> 2) + ((e >> 1) << 3);
                    *reinterpret_cast<float2*>(
                        out + ((size_t)(row0 + row) * Tt + t) * Uu + ucol) =
                        make_float2(gv[j], gv[j + 1]);
                }
                if (half == 0) {   // stash half-0 h in smem until step end
#pragma unroll
                    for (int q = 0; q < 4; q++)
                        *reinterpret_cast<float4*>(holdSm + 4 * q) =
                            make_float4(gv[4 * q], gv[4 * q + 1],
                                        gv[4 * q + 2], gv[4 * q + 3]);
                }
            }
        } // sweeps

        // ---- step boundary: write h (both halves) back into A, load x(t+1) ----
        __syncthreads();   // all A reads of this step complete
#pragma unroll
        for (int j = 0; j < 16; j++) {
            const int mt = j >> 3, nt = (j >> 2) & 1, e = j & 3;
            const int loc = wn * 16 + nt * 8 + 2 * (lane & 3) + (e & 1);
            const int row = wm * 32 + mt * 16 + (lane >> 2) + ((e >> 1) << 3);
            a_store(sm, row, 128 + loc, gv[j]);        // half 1 (in regs)
            a_store(sm, row, loc,       holdSm[j]);    // half 0 (from smem)
        }
        if (t + 1 < Tt) {
            for (int i = tid; i < BMr * Ff; i += NTm) {
                int r = i / Ff, f = i - r * Ff;
                a_store(sm, r, 256 + f,
                        x[((size_t)(row0 + r) * Tt + (t + 1)) * Ff + f]);
            }
        }
        __syncthreads();
    } // t
}

// ---------------------------------------------------------------------------
// Harness entry point
// ---------------------------------------------------------------------------
extern "C" void kernel_launch(void* const* d_in, const int* in_sizes, int n_in,
                              void* d_out, int out_size) {
    const float* x  = (const float*)d_in[0];  // [B,T,F]
    const float* h0 = (const float*)d_in[1];  // [B,U]
    const float* c0 = (const float*)d_in[2];  // [B,U]
    const float* Wk = (const float*)d_in[3];  // [F,4U]
    const float* Wr = (const float*)d_in[4];  // [U,4U]
    const float* b  = (const float*)d_in[5];  // [4U]
    float* out = (float*)d_out;               // [B,T,U]

    prep_kernel<<<(4 * NCH * 4 * 1024 + 511) / 512, 512>>>(Wr, Wk);

    cudaFuncSetAttribute(lstm_hmma,
                         cudaFuncAttributeMaxDynamicSharedMemorySize, SMEM_TOTAL);
    lstm_hmma<<<NCTA, NTm, SMEM_TOTAL>>>(x, h0, c0, b, out);
}

// round 14
// speedup vs baseline: 3.2066x; 1.8627x over previous
#include <cuda_runtime.h>
#include <cuda_fp16.h>

typedef unsigned int u32;

// ---------------- problem constants ----------------
#define Tt   7
#define Ff   36
#define Uu   256
#define Bsz  32768
#define BMr  64             // batch rows per CTA (2 m-warp rows x 32)
#define NTm  512            // 16 warps = 2M x 8N
#define NCTA 512            // Bsz / BMr
#define KPAD 320            // 256 h + 36 x + 28 pad = 20 k16 chunks (EVEN)
#define NCH  20
#define SPAD 328            // A row stride in fp16: 656B, 16B-aligned, staggered
#define ROWB (SPAD * 2)     // 656 bytes per A row
#define CPS  (4 * NCH)      // 80 chunks per step

// ---------------- smem layout ----------------
#define AH_OFF   0                         // A: 64 x 656B = 41984
#define HOLD_OFF (BMr * ROWB)              // 41984: half-0 h buffer (32KB)
#define C_OFF    (HOLD_OFF + NTm * 16 * 4) // 74752: c state (64KB)
#define SMEM_TOTAL (C_OFF + NTm * 32 * 4)  // 140288

// ---------------- device scratch (static) ----------------
// B fragments (single fp16 term) in CONSUMPTION order:
// [(s*NCH+cc)*2 + gsel]*1024 + wn*128 + lane*4 + reg
__device__ u32 g_Bfrag[4 * NCH * 2 * 1024];   // 640KB, L2-resident

// ---------------- ptx helpers ----------------
__device__ __forceinline__ u32 smem_u32(const void* p) {
    u32 a;
    asm("{ .reg .u64 t; cvta.to.shared.u64 t, %1; cvt.u32.u64 %0, t; }"
        : "=r"(a) : "l"(p));
    return a;
}
__device__ __forceinline__ float fsgm(float z) {
    float e, r;
    asm("ex2.approx.f32 %0, %1;" : "=f"(e) : "f"(-1.4426950408889634f * z));
    asm("rcp.approx.f32 %0, %1;" : "=f"(r) : "f"(1.0f + e));
    return r;
}
__device__ __forceinline__ float ftanh(float z) {
    float e, r;
    asm("ex2.approx.f32 %0, %1;" : "=f"(e) : "f"(-2.8853900817779268f * z));
    asm("rcp.approx.f32 %0, %1;" : "=f"(r) : "f"(1.0f + e));
    return fmaf(2.0f, r, -1.0f);
}
__device__ __forceinline__ void ldm4(u32* r, u32 addr) {
    asm volatile("ldmatrix.sync.aligned.m8n8.x4.shared.b16 {%0,%1,%2,%3}, [%4];"
                 : "=r"(r[0]), "=r"(r[1]), "=r"(r[2]), "=r"(r[3]) : "r"(addr));
}
__device__ __forceinline__ void mma16816(float* d, const u32* a, const u32* b) {
    asm volatile(
        "mma.sync.aligned.m16n8k16.row.col.f32.f16.f16.f32 "
        "{%0,%1,%2,%3}, {%4,%5,%6,%7}, {%8,%9}, {%0,%1,%2,%3};"
        : "+f"(d[0]), "+f"(d[1]), "+f"(d[2]), "+f"(d[3])
        : "r"(a[0]), "r"(a[1]), "r"(a[2]), "r"(a[3]), "r"(b[0]), "r"(b[1]));
}
__device__ __forceinline__ void ldg4(u32* r, const u32* p) {
    asm volatile("ld.global.nc.v4.u32 {%0,%1,%2,%3}, [%4];"
                 : "=r"(r[0]), "=r"(r[1]), "=r"(r[2]), "=r"(r[3]) : "l"(p));
}

// A store helper: fp16 at A[r][k]
__device__ __forceinline__ void a_store(char* sm, int r, int k, float v) {
    *reinterpret_cast<__half*>(sm + AH_OFF + r * ROWB + k * 2) = __float2half(v);
}

// ---------------------------------------------------------------------------
// prep: pack W = [Wr;Wk;0] into mma B-fragment order, single fp16,
// grouped by fused sweep: s in 0..3 -> half = s>>1, pair = s&1;
// pair 0 -> gates (i=0, g=2); pair 1 -> gates (f=1, o=3).
// ---------------------------------------------------------------------------
__global__ void prep_kernel(const float* __restrict__ Wr,
                            const float* __restrict__ Wk) {
    int idx = blockIdx.x * 512 + threadIdx.x;
    if (idx >= 4 * NCH * 2 * 1024) return;
    int reg  = idx & 3;
    int lane = (idx >> 2) & 31;
    int wn   = (idx >> 7) & 7;
    int rest = idx >> 10;
    int gsel = rest & 1;
    int bc   = rest >> 1;
    int cc   = bc % NCH;
    int s    = bc / NCH;           // 0..3

    int half = s >> 1;
    int pair = s & 1;
    int gate = (pair == 0) ? (gsel ? 2 : 0) : (gsel ? 3 : 1);

    int n_local = wn * 16 + (reg >> 1) * 8 + (lane >> 2);
    int ncol    = gate * 256 + half * 128 + n_local;
    int k0      = cc * 16 + (reg & 1) * 8 + ((lane & 3) << 1);

    float v0 = 0.f, v1 = 0.f;
    if (k0 < 256)      v0 = Wr[(size_t)k0 * 1024 + ncol];
    else if (k0 < 292) v0 = Wk[(size_t)(k0 - 256) * 1024 + ncol];
    int k1 = k0 + 1;
    if (k1 < 256)      v1 = Wr[(size_t)k1 * 1024 + ncol];
    else if (k1 < 292) v1 = Wk[(size_t)(k1 - 256) * 1024 + ncol];

    unsigned short e0 = __half_as_ushort(__float2half(v0));
    unsigned short e1 = __half_as_ushort(__float2half(v1));
    g_Bfrag[idx] = ((u32)e1 << 16) | (u32)e0;
}

// chunk-worth of HMMAs consuming buffer pf (8 u32: gsel0 regs0-3, gsel1 regs0-3)
#define DO_CHUNK(cc, pf)                                                    \
    do {                                                                    \
        const u32 ao = aBase + (u32)(cc) * 32;                              \
        u32 a0[4], a1[4];                                                   \
        ldm4(a0, ao);                                                       \
        ldm4(a1, ao + 16 * ROWB);                                           \
        _Pragma("unroll")                                                   \
        for (int g = 0; g < 2; g++)                                         \
            _Pragma("unroll")                                               \
            for (int nt = 0; nt < 2; nt++) {                                \
                mma16816(acc[g][0][nt], a0, &(pf)[g * 4 + nt * 2]);         \
                mma16816(acc[g][1][nt], a1, &(pf)[g * 4 + nt * 2]);         \
            }                                                               \
    } while (0)

#define PREFETCH(pf)                                                        \
    do {                                                                    \
        const u32* _p = bBase + (size_t)pi * 2048;                          \
        ldg4(&(pf)[0], _p);                                                 \
        ldg4(&(pf)[4], _p + 1024);                                          \
        if (++pi == CPS) pi = 0;                                            \
    } while (0)

// ---------------------------------------------------------------------------
// main LSTM kernel: fused gate pairs, fp16 1-term, double-buffered B, c in smem
// ---------------------------------------------------------------------------
__global__ void __launch_bounds__(NTm, 1)
lstm_hmma(const float* __restrict__ x,    // [B,T,F]
          const float* __restrict__ h0,   // [B,U]
          const float* __restrict__ c0,   // [B,U]
          const float* __restrict__ bia,  // [4U]
          float* __restrict__ out)        // [B,T,U]
{
    extern __shared__ char sm[];
    const u32 smb  = smem_u32(sm);
    const int tid  = threadIdx.x;
    const int lane = tid & 31;
    const int wid  = tid >> 5;
    const int wm   = wid >> 3;       // 0..1  (M warp row)
    const int wn   = wid & 7;        // 0..7  (N warp col)
    const int cta  = blockIdx.x;
    const int row0 = cta * BMr;
    float* holdSm = reinterpret_cast<float*>(sm + HOLD_OFF) + tid * 16;
    float* cSm    = reinterpret_cast<float*>(sm + C_OFF);

    // ---- init A: h0 (fp16), x(t=0), zero pad ----
    for (int i = tid; i < BMr * Uu; i += NTm) {
        int r = i >> 8, k = i & 255;
        a_store(sm, r, k, h0[(size_t)(row0 + r) * Uu + k]);
    }
    for (int i = tid; i < BMr * Ff; i += NTm) {
        int r = i / Ff, f = i - r * Ff;
        a_store(sm, r, 256 + f, x[(size_t)(row0 + r) * (Tt * Ff) + f]);
    }
    for (int i = tid; i < BMr * (KPAD - 292); i += NTm) {
        int r = i / (KPAD - 292), k = 292 + (i - r * (KPAD - 292));
        a_store(sm, r, k, 0.0f);
    }

    // ---- init c state in smem (this thread's 32 lattice points) ----
#pragma unroll
    for (int j = 0; j < 32; j++) {
        const int half = j >> 4, jj = j & 15;
        const int mt = jj >> 3, nt = (jj >> 2) & 1, e = jj & 3;
        const int ucol = half * 128 + wn * 16 + nt * 8 + 2 * (lane & 3) + (e & 1);
        const int row  = wm * 32 + mt * 16 + (lane >> 2) + ((e >> 1) << 3);
        cSm[j * NTm + tid] = c0[(size_t)(row0 + row) * Uu + ucol];
    }
    __syncthreads();

    // ldmatrix per-lane base address (m-tile 0)
    const u32 aBase = smb + AH_OFF
                    + (u32)(wm * 32 + (lane & 15)) * ROWB
                    + (u32)((lane >> 4) * 16);

    // ---- B double-buffer: pfA = even chunks, pfB = odd chunks ----
    const u32* bBase = g_Bfrag + (wn * 128 + lane * 4);
    int pi = 0;
    u32 pfA[8], pfB[8];
    PREFETCH(pfA);     // chunk 0
    PREFETCH(pfB);     // chunk 1

    float gv[16];

#pragma unroll 1
    for (int t = 0; t < Tt; t++) {
#pragma unroll 1
        for (int s = 0; s < 4; s++) {
            const int half = s >> 1;
            const int pair = s & 1;

            float acc[2][2][2][4];   // [gate][mt][nt][e]
#pragma unroll
            for (int g = 0; g < 2; g++)
#pragma unroll
                for (int a = 0; a < 2; a++)
#pragma unroll
                    for (int b = 0; b < 2; b++)
#pragma unroll
                        for (int e = 0; e < 4; e++) acc[g][a][b][e] = 0.f;

            // ---- mainloop: 20 chunks, double-buffered, no barriers ----
#pragma unroll 1
            for (int cc = 0; cc < NCH; cc += 2) {
                DO_CHUNK(cc, pfA);
                PREFETCH(pfA);           // refill: 2 chunks ahead
                DO_CHUNK(cc + 1, pfB);
                PREFETCH(pfB);
            }

            // ---- fused epilogue ----
            const int g0 = pair ? 1 : 0;   // i or f
            const int g1 = pair ? 3 : 2;   // g or o
#pragma unroll
            for (int j = 0; j < 16; j++) {
                const int mt = j >> 3, nt = (j >> 2) & 1, e = j & 3;
                const int ucol = half * 128 + wn * 16 + nt * 8
                               + 2 * (lane & 3) + (e & 1);
                const float z0 = acc[0][mt][nt][e] + __ldg(bia + g0 * 256 + ucol);
                const float z1 = acc[1][mt][nt][e] + __ldg(bia + g1 * 256 + ucol);
                if (pair == 0) {
                    gv[j] = fsgm(z0) * ftanh(z1);      // sigma(i)*tanh(g)
                } else {
                    float* cp = &cSm[(half * 16 + j) * NTm + tid];
                    const float cn = fsgm(z0) * (*cp) + gv[j];
                    *cp = cn;
                    gv[j] = fsgm(z1) * ftanh(cn);      // h = sigma(o)*tanh(c)
                }
            }

            if (pair == 1) {
                // write h to out (float2 pairs share a row)
#pragma unroll
                for (int jp = 0; jp < 8; jp++) {
                    const int j  = 2 * jp;
                    const int mt = j >> 3, nt = (j >> 2) & 1, e = j & 3;
                    const int ucol = half * 128 + wn * 16 + nt * 8 + 2 * (lane & 3);
                    const int row  = wm * 32 + mt * 16 + (lane >> 2) + ((e >> 1) << 3);
                    *reinterpret_cast<float2*>(
                        out + ((size_t)(row0 + row) * Tt + t) * Uu + ucol) =
                        make_float2(gv[j], gv[j + 1]);
                }
                if (half == 0) {   // stash half-0 h in smem until step end
#pragma unroll
                    for (int q = 0; q < 4; q++)
                        *reinterpret_cast<float4*>(holdSm + 4 * q) =
                            make_float4(gv[4 * q], gv[4 * q + 1],
                                        gv[4 * q + 2], gv[4 * q + 3]);
                }
            }
        } // sweeps

        // ---- step boundary: write h (both halves) back into A, load x(t+1) ----
        __syncthreads();   // all A reads of this step complete
#pragma unroll
        for (int j = 0; j < 16; j++) {
            const int mt = j >> 3, nt = (j >> 2) & 1, e = j & 3;
            const int loc = wn * 16 + nt * 8 + 2 * (lane & 3) + (e & 1);
            const int row = wm * 32 + mt * 16 + (lane >> 2) + ((e >> 1) << 3);
            a_store(sm, row, 128 + loc, gv[j]);        // half 1 (in regs)
            a_store(sm, row, loc,       holdSm[j]);    // half 0 (from smem)
        }
        if (t + 1 < Tt) {
            for (int i = tid; i < BMr * Ff; i += NTm) {
                int r = i / Ff, f = i - r * Ff;
                a_store(sm, r, 256 + f,
                        x[((size_t)(row0 + r) * Tt + (t + 1)) * Ff + f]);
            }
        }
        __syncthreads();
    } // t
}

// ---------------------------------------------------------------------------
// Harness entry point
// ---------------------------------------------------------------------------
extern "C" void kernel_launch(void* const* d_in, const int* in_sizes, int n_in,
                              void* d_out, int out_size) {
    const float* x  = (const float*)d_in[0];  // [B,T,F]
    const float* h0 = (const float*)d_in[1];  // [B,U]
    const float* c0 = (const float*)d_in[2];  // [B,U]
    const float* Wk = (const float*)d_in[3];  // [F,4U]
    const float* Wr = (const float*)d_in[4];  // [U,4U]
    const float* b  = (const float*)d_in[5];  // [4U]
    float* out = (float*)d_out;               // [B,T,U]

    prep_kernel<<<(4 * NCH * 2 * 1024 + 511) / 512, 512>>>(Wr, Wk);

    cudaFuncSetAttribute(lstm_hmma,
                         cudaFuncAttributeMaxDynamicSharedMemorySize, SMEM_TOTAL);
    lstm_hmma<<<NCTA, NTm, SMEM_TOTAL>>>(x, h0, c0, b, out);
}